// round 16
// baseline (speedup 1.0000x reference)
#include <cuda_runtime.h>
#include <cuda_fp16.h>
#include <cstdint>

#define SEQ 2048
#define DM  4096
#define NH  32
#define NKV 8
#define HD  128
#define KVD (NKV*HD)
#define NEG_BIG -1.0e9f

// half scratch buffers (static device globals)
__device__ __half g_xh [SEQ*DM];
__device__ __half g_wqh[DM*DM];
__device__ __half g_wkh[KVD*DM];
__device__ __half g_wvh[KVD*DM];
__device__ __half g_woh[DM*DM];
__device__ __half g_qh [SEQ*DM];
__device__ __half g_kh [SEQ*KVD];
__device__ __half g_vh [SEQ*KVD];
__device__ __half g_ath[SEQ*DM];

// ---------------------------------------------------------------------------
// helpers
// ---------------------------------------------------------------------------
__device__ __forceinline__ uint32_t smem_u32(const void* p) {
    uint32_t a;
    asm("{ .reg .u64 t; cvta.to.shared.u64 t, %1; cvt.u32.u64 %0, t; }"
        : "=r"(a) : "l"(p));
    return a;
}
__device__ __forceinline__ uint32_t h2pack(float a, float b) {
    __half2 h = __floats2half2_rn(a, b);
    return *reinterpret_cast<uint32_t*>(&h);
}
__device__ __forceinline__ float ex2(float x) {
    float y;
    asm("ex2.approx.f32 %0, %1;" : "=f"(y) : "f"(x));
    return y;
}
__device__ __forceinline__ void cpa16(uint32_t dst, const void* src) {
    asm volatile("cp.async.cg.shared.global [%0], [%1], 16;"
                 :: "r"(dst), "l"(src));
}
__device__ __forceinline__ void cp_commit() {
    asm volatile("cp.async.commit_group;" ::: "memory");
}
__device__ __forceinline__ void ldsm4(uint32_t* r, uint32_t addr) {
    asm volatile("ldmatrix.sync.aligned.m8n8.x4.shared.b16 {%0,%1,%2,%3}, [%4];"
                 : "=r"(r[0]), "=r"(r[1]), "=r"(r[2]), "=r"(r[3]) : "r"(addr));
}
__device__ __forceinline__ void ldsm4t(uint32_t* r, uint32_t addr) {
    asm volatile("ldmatrix.sync.aligned.m8n8.x4.trans.shared.b16 {%0,%1,%2,%3}, [%4];"
                 : "=r"(r[0]), "=r"(r[1]), "=r"(r[2]), "=r"(r[3]) : "r"(addr));
}
__device__ __forceinline__ void mma_f16(float* d, const uint32_t* a,
                                        const uint32_t* b) {
    asm volatile(
        "mma.sync.aligned.m16n8k16.row.col.f32.f16.f16.f32 "
        "{%0,%1,%2,%3},{%4,%5,%6,%7},{%8,%9},{%0,%1,%2,%3};"
        : "+f"(d[0]), "+f"(d[1]), "+f"(d[2]), "+f"(d[3])
        : "r"(a[0]), "r"(a[1]), "r"(a[2]), "r"(a[3]), "r"(b[0]), "r"(b[1]));
}

// ---------------------------------------------------------------------------
// fused fp32 -> fp16 convert of all five tensors, ILP 4
// ---------------------------------------------------------------------------
#define F4_X  2097152
#define F4_WQ 4194304
#define F4_KV 1048576
#define F4_C0 (F4_X)
#define F4_C1 (F4_C0 + F4_WQ)
#define F4_C2 (F4_C1 + F4_KV)
#define F4_C3 (F4_C2 + F4_KV)
#define F4_C4 (F4_C3 + F4_WQ)
#define F2H_BLOCKS (F4_C4 / 1024)

__global__ void f2h_all(const float* __restrict__ x,  const float* __restrict__ wq,
                        const float* __restrict__ wk, const float* __restrict__ wv,
                        const float* __restrict__ wo,
                        __half* xh, __half* wqh, __half* wkh, __half* wvh, __half* woh)
{
    size_t base = (size_t)blockIdx.x * 1024 + threadIdx.x;  // float4 index
    const float* s;
    __half* d;
    size_t off;
    if (base < F4_C0)      { s = x;  d = xh;  off = base; }
    else if (base < F4_C1) { s = wq; d = wqh; off = base - F4_C0; }
    else if (base < F4_C2) { s = wk; d = wkh; off = base - F4_C1; }
    else if (base < F4_C3) { s = wv; d = wvh; off = base - F4_C2; }
    else                   { s = wo; d = woh; off = base - F4_C3; }
#pragma unroll
    for (int j = 0; j < 4; j++) {
        size_t o4 = off + (size_t)j * 256;
        float4 v = *(const float4*)(s + o4 * 4);
        *(uint2*)(d + o4 * 4) = make_uint2(h2pack(v.x, v.y), h2pack(v.z, v.w));
    }
}

// ---------------------------------------------------------------------------
// GEMM core v7: CTA 256x128, kc=32, 256 thr = 8 warps (4Mx2N), warp 64x64,
// cp.async 3-stage, wait+sync per chunk, ldmatrix burst, fp32-acc fp16 mma.
// 2 CTAs/SM = 16 warps (4/SMSP) for latency cover; B reused 4x, A 2x.
// A tile 256x32h (5120 words @stride 20), B tile 128x32h (2560 words).
// ---------------------------------------------------------------------------
#define GAW  5120                  // A tile words
#define GSTW 7680                  // stage words (A+B)
#define GEMM_SMEM (3*GSTW*4)       // 92160 B; 2 CTAs = 180 KB <= 228 KB

#define GEMM_PRE()                                                             \
    extern __shared__ uint32_t smq[];                                          \
    const uint32_t sb = smem_u32(smq);                                         \
    const int tid  = threadIdx.x;                                              \
    const int lane = tid & 31;                                                 \
    const int warp = tid >> 5;                                                 \
    const int wm = warp & 3, wn = warp >> 2;                                   \
    const int l7 = lane & 7, l8 = (lane >> 3) & 1, l16 = lane >> 4;            \
    const int lg = lane >> 2, lc = lane & 3;                                   \
    const int r0 = tid >> 2, c0 = tid & 3;                                     \
    uint32_t dA[4], dB[2];                                                     \
    _Pragma("unroll")                                                          \
    for (int i = 0; i < 4; i++)                                                \
        dA[i] = (uint32_t)((r0 + 64 * i) * 20 + c0 * 4) * 4;                   \
    _Pragma("unroll")                                                          \
    for (int i = 0; i < 2; i++)                                                \
        dB[i] = (uint32_t)(GAW + (r0 + 64 * i) * 20 + c0 * 4) * 4;             \
    const uint32_t aoff = (uint32_t)((wm * 64 + l7 + 8 * l8) * 20 + 4 * l16) * 4; \
    const uint32_t boff = (uint32_t)(GAW + (wn * 64 + l7 + 8 * l16) * 20 + 4 * l8) * 4;

#define GLOAD(stage, koff)                                                     \
    {                                                                          \
        uint32_t base_ = sb + (uint32_t)(stage) * GSTW * 4;                    \
        _Pragma("unroll")                                                      \
        for (int i_ = 0; i_ < 4; i_++)                                         \
            cpa16(base_ + dA[i_], Ab + (size_t)(64 * i_) * DM + (koff));       \
        _Pragma("unroll")                                                      \
        for (int i_ = 0; i_ < 2; i_++)                                         \
            cpa16(base_ + dB[i_], Bb + (size_t)(64 * i_) * DM + (koff));       \
        cp_commit();                                                           \
    }

#define GEMM_BODY()                                                            \
    float acc[4][8][4];                                                        \
    _Pragma("unroll")                                                          \
    for (int mi = 0; mi < 4; mi++)                                             \
        _Pragma("unroll")                                                      \
        for (int ni = 0; ni < 8; ni++)                                         \
            _Pragma("unroll")                                                  \
            for (int r = 0; r < 4; r++) acc[mi][ni][r] = 0.f;                  \
    const int kiters = DM / 32;                                                \
    GLOAD(0, 0);                                                               \
    GLOAD(1, 32);                                                              \
    int st = 0;                                                                \
    for (int kt = 0; kt < kiters; kt++) {                                      \
        if (kt + 1 < kiters)                                                   \
            asm volatile("cp.async.wait_group 1;" ::: "memory");               \
        else                                                                   \
            asm volatile("cp.async.wait_group 0;" ::: "memory");               \
        __syncthreads();                                                       \
        if (kt + 2 < kiters) {                                                 \
            int s2 = st + 2; if (s2 >= 3) s2 -= 3;                             \
            GLOAD(s2, (kt + 2) * 32);                                          \
        }                                                                      \
        const uint32_t sbase = sb + (uint32_t)st * GSTW * 4;                   \
        uint32_t b0f[4][4], b1f[4][4], a0f[4][4], a1f[4][4];                   \
        _Pragma("unroll")                                                      \
        for (int j = 0; j < 4; j++) ldsm4(b0f[j], sbase + boff + j * 1280);    \
        _Pragma("unroll")                                                      \
        for (int j = 0; j < 4; j++) ldsm4(a0f[j], sbase + aoff + j * 1280);    \
        _Pragma("unroll")                                                      \
        for (int j = 0; j < 4; j++) ldsm4(b1f[j], sbase + boff + j * 1280 + 32); \
        _Pragma("unroll")                                                      \
        for (int j = 0; j < 4; j++) ldsm4(a1f[j], sbase + aoff + j * 1280 + 32); \
        _Pragma("unroll")                                                      \
        for (int mi = 0; mi < 4; mi++)                                         \
            _Pragma("unroll")                                                  \
            for (int nj = 0; nj < 4; nj++) {                                   \
                mma_f16(acc[mi][2 * nj],     a0f[mi], b0f[nj]);                \
                mma_f16(acc[mi][2 * nj + 1], a0f[mi], b0f[nj] + 2);            \
            }                                                                  \
        _Pragma("unroll")                                                      \
        for (int mi = 0; mi < 4; mi++)                                         \
            _Pragma("unroll")                                                  \
            for (int nj = 0; nj < 4; nj++) {                                   \
                mma_f16(acc[mi][2 * nj],     a1f[mi], b1f[nj]);                \
                mma_f16(acc[mi][2 * nj + 1], a1f[mi], b1f[nj] + 2);            \
            }                                                                  \
        if (++st == 3) st = 0;                                                 \
    }

// fused QKV with rope epilogue on Q/K (M block = 256 rows)
__global__ __launch_bounds__(256, 2) void qkv_gemm(
    const __half* __restrict__ Aq,
    const __half* __restrict__ wq, const __half* __restrict__ wk,
    const __half* __restrict__ wv,
    __half* __restrict__ qo, __half* __restrict__ ko, __half* __restrict__ vo,
    const float* __restrict__ fcos, const float* __restrict__ fsin)
{
    GEMM_PRE();
    int bx = blockIdx.x;
    const __half* Bsel;
    __half* Csel;
    int Nc, cb;
    bool rope;
    if (bx < 32)      { Bsel = wq; Csel = qo; Nc = DM;  cb = bx;      rope = true; }
    else if (bx < 40) { Bsel = wk; Csel = ko; Nc = KVD; cb = bx - 32; rope = true; }
    else              { Bsel = wv; Csel = vo; Nc = KVD; cb = bx - 40; rope = false; }

    const __half* Ab = Aq + (size_t)(blockIdx.y * 256 + r0) * DM + c0 * 8;
    const __half* Bb = Bsel + (size_t)(cb * 128 + r0) * DM + c0 * 8;

    GEMM_BODY();

#pragma unroll
    for (int mi = 0; mi < 4; mi++) {
        int r = blockIdx.y * 256 + wm * 64 + mi * 16 + lg;
#pragma unroll
        for (int ni = 0; ni < 8; ni++) {
            int c = cb * 128 + wn * 64 + ni * 8 + lc * 2;
            float e0 = acc[mi][ni][0], e1 = acc[mi][ni][1];
            float e2 = acc[mi][ni][2], e3 = acc[mi][ni][3];
            if (rope) {
                int pidx = wn * 32 + ni * 4 + lc;   // pair index within head
                float c0f = fcos[r * 64 + pidx];
                float s0f = fsin[r * 64 + pidx];
                float c1f = fcos[(r + 8) * 64 + pidx];
                float s1f = fsin[(r + 8) * 64 + pidx];
                float t0 = e0 * c0f - e1 * s0f;
                float t1 = e0 * s0f + e1 * c0f;
                float t2 = e2 * c1f - e3 * s1f;
                float t3 = e2 * s1f + e3 * c1f;
                e0 = t0; e1 = t1; e2 = t2; e3 = t3;
            }
            *(uint32_t*)&Csel[(size_t)r * Nc + c]       = h2pack(e0, e1);
            *(uint32_t*)&Csel[(size_t)(r + 8) * Nc + c] = h2pack(e2, e3);
        }
    }
}

// O-projection: half in, float out (M block = 256 rows)
__global__ __launch_bounds__(256, 2) void gemm_of(
    const __half* __restrict__ A, const __half* __restrict__ B,
    float* __restrict__ C)
{
    GEMM_PRE();
    const int N = DM;
    const __half* Ab = A + (size_t)(blockIdx.y * 256 + r0) * DM + c0 * 8;
    const __half* Bb = B + (size_t)(blockIdx.x * 128 + r0) * DM + c0 * 8;

    GEMM_BODY();

#pragma unroll
    for (int mi = 0; mi < 4; mi++) {
        int r = blockIdx.y * 256 + wm * 64 + mi * 16 + lg;
#pragma unroll
        for (int ni = 0; ni < 8; ni++) {
            int c = blockIdx.x * 128 + wn * 64 + ni * 8 + lc * 2;
            *(float2*)&C[(size_t)r * N + c] =
                make_float2(acc[mi][ni][0], acc[mi][ni][1]);
            *(float2*)&C[(size_t)(r + 8) * N + c] =
                make_float2(acc[mi][ni][2], acc[mi][ni][3]);
        }
    }
}

// ---------------------------------------------------------------------------
// flash attention v6 (validated R12): BN=128, BM=128 (8 warps x 16 q rows),
// fp16 mma fp32-acc, base-2 online softmax, P-in-registers,
// cp.async double-buffered K/V (wait+sync per consumed tile).
// ---------------------------------------------------------------------------
#define QW  (128*68)
#define FTW (128*68)
#define FLASH_SMEM ((QW + 4*FTW)*4)

__global__ __launch_bounds__(256, 1) void flash_h(
    const __half* __restrict__ q, const __half* __restrict__ k,
    const __half* __restrict__ v, __half* __restrict__ outh)
{
    extern __shared__ uint32_t fsm[];
    const uint32_t sb = smem_u32(fsm);

    const int h   = blockIdx.y;
    const int qb  = gridDim.x - 1 - blockIdx.x;
    const int q0  = qb * 128;
    const int kvh = h >> 2;
    const int tid = threadIdx.x;
    const int warp = tid >> 5;
    const int lane = tid & 31;
    const int l7 = lane & 7, l8 = (lane >> 3) & 1, l16 = lane >> 4;
    const int lg = lane >> 2, lc = lane & 3;

    const int rb = tid >> 4, cch = tid & 15;

#pragma unroll
    for (int i = 0; i < 8; i++) {
        int r = i * 16 + rb;
        cpa16(sb + (uint32_t)(r * 68 + cch * 4) * 4,
              q + (size_t)(q0 + r) * DM + h * HD + cch * 8);
    }
#pragma unroll
    for (int i = 0; i < 8; i++) {
        int r = i * 16 + rb;
        cpa16(sb + (uint32_t)(QW + r * 68 + cch * 4) * 4,
              k + (size_t)r * KVD + kvh * HD + cch * 8);
        cpa16(sb + (uint32_t)(QW + 2 * FTW + r * 68 + cch * 4) * 4,
              v + (size_t)r * KVD + kvh * HD + cch * 8);
    }
    cp_commit();

    const uint32_t Qa = (uint32_t)((warp * 16 + l7 + 8 * l8) * 68 + 4 * l16) * 4;
    const uint32_t Kb = (uint32_t)((l7 + 8 * l16) * 68 + 4 * l8) * 4;
    const uint32_t Vb = (uint32_t)((l7 + 8 * l8) * 68 + 4 * l16) * 4;

    float o[16][4];
#pragma unroll
    for (int ni = 0; ni < 16; ni++)
#pragma unroll
        for (int r = 0; r < 4; r++) o[ni][r] = 0.f;
    float m0 = -3.0e38f, m1 = -3.0e38f, l0 = 0.f, l1 = 0.f;

    const float sc2 = 0.12751741f;   // 1/sqrt(128) * log2(e)
    const int rowl0 = warp * 16 + lg;

    for (int kb = 0; kb <= qb; kb++) {
        const int k0g = kb * 128;
        asm volatile("cp.async.wait_group 0;" ::: "memory");
        __syncthreads();

        if (kb + 1 <= qb) {
            const int k0n = (kb + 1) * 128;
            const uint32_t bufn = (uint32_t)((kb + 1) & 1) * FTW;
#pragma unroll
            for (int i = 0; i < 8; i++) {
                int r = i * 16 + rb;
                cpa16(sb + (QW + bufn + (uint32_t)(r * 68 + cch * 4)) * 4,
                      k + (size_t)(k0n + r) * KVD + kvh * HD + cch * 8);
                cpa16(sb + (QW + 2 * FTW + bufn + (uint32_t)(r * 68 + cch * 4)) * 4,
                      v + (size_t)(k0n + r) * KVD + kvh * HD + cch * 8);
            }
            cp_commit();
        }

        const uint32_t bufK = sb + (QW + (uint32_t)(kb & 1) * FTW) * 4;
        const uint32_t bufV = sb + (QW + 2 * FTW + (uint32_t)(kb & 1) * FTW) * 4;

        float s[16][4];
#pragma unroll
        for (int ni = 0; ni < 16; ni++)
#pragma unroll
            for (int r = 0; r < 4; r++) s[ni][r] = 0.f;

        uint32_t qaf[2][4];
        ldsm4(qaf[0], sb + Qa);
#pragma unroll
        for (int kd = 0; kd < 8; kd++) {
            if (kd < 7) ldsm4(qaf[(kd + 1) & 1], sb + Qa + (kd + 1) * 32);
            const uint32_t* qa = qaf[kd & 1];
#pragma unroll
            for (int nj = 0; nj < 8; nj++) {
                uint32_t kb4[4];
                ldsm4(kb4, bufK + Kb + nj * (16 * 68 * 4) + kd * 32);
                mma_f16(s[2 * nj],     qa, kb4);
                mma_f16(s[2 * nj + 1], qa, kb4 + 2);
            }
        }

        const bool diag = (kb == qb);
        float mx0 = -3.0e38f, mx1 = -3.0e38f;
#pragma unroll
        for (int ni = 0; ni < 16; ni++) {
            float v0 = s[ni][0] * sc2, v1 = s[ni][1] * sc2;
            float v2 = s[ni][2] * sc2, v3 = s[ni][3] * sc2;
            if (diag) {
                int cl = k0g + ni * 8 + 2 * lc;
                if (cl     > (q0 + rowl0))     v0 += NEG_BIG;
                if (cl + 1 > (q0 + rowl0))     v1 += NEG_BIG;
                if (cl     > (q0 + rowl0 + 8)) v2 += NEG_BIG;
                if (cl + 1 > (q0 + rowl0 + 8)) v3 += NEG_BIG;
            }
            s[ni][0] = v0; s[ni][1] = v1; s[ni][2] = v2; s[ni][3] = v3;
            mx0 = fmaxf(mx0, fmaxf(v0, v1));
            mx1 = fmaxf(mx1, fmaxf(v2, v3));
        }
        mx0 = fmaxf(mx0, __shfl_xor_sync(0xffffffffu, mx0, 1));
        mx0 = fmaxf(mx0, __shfl_xor_sync(0xffffffffu, mx0, 2));
        mx1 = fmaxf(mx1, __shfl_xor_sync(0xffffffffu, mx1, 1));
        mx1 = fmaxf(mx1, __shfl_xor_sync(0xffffffffu, mx1, 2));

        float mn0 = fmaxf(m0, mx0), mn1 = fmaxf(m1, mx1);
        float a0 = ex2(m0 - mn0), a1 = ex2(m1 - mn1);
        m0 = mn0; m1 = mn1;

        float sum0 = 0.f, sum1 = 0.f;
#pragma unroll
        for (int ni = 0; ni < 16; ni++) {
            float p0 = ex2(s[ni][0] - m0);
            float p1 = ex2(s[ni][1] - m0);
            float p2 = ex2(s[ni][2] - m1);
            float p3 = ex2(s[ni][3] - m1);
            s[ni][0] = p0; s[ni][1] = p1; s[ni][2] = p2; s[ni][3] = p3;
            sum0 += p0 + p1;
            sum1 += p2 + p3;
        }
        sum0 += __shfl_xor_sync(0xffffffffu, sum0, 1);
        sum0 += __shfl_xor_sync(0xffffffffu, sum0, 2);
        sum1 += __shfl_xor_sync(0xffffffffu, sum1, 1);
        sum1 += __shfl_xor_sync(0xffffffffu, sum1, 2);
        l0 = l0 * a0 + sum0;
        l1 = l1 * a1 + sum1;

#pragma unroll
        for (int ni = 0; ni < 16; ni++) {
            o[ni][0] *= a0; o[ni][1] *= a0;
            o[ni][2] *= a1; o[ni][3] *= a1;
        }

#pragma unroll
        for (int ks = 0; ks < 8; ks++) {
            uint32_t pa[4];
            pa[0] = h2pack(s[2 * ks][0],     s[2 * ks][1]);
            pa[1] = h2pack(s[2 * ks][2],     s[2 * ks][3]);
            pa[2] = h2pack(s[2 * ks + 1][0], s[2 * ks + 1][1]);
            pa[3] = h2pack(s[2 * ks + 1][2], s[2 * ks + 1][3]);
#pragma unroll
            for (int dj = 0; dj < 8; dj++) {
                uint32_t vb4[4];
                ldsm4t(vb4, bufV + Vb + ks * (16 * 68 * 4) + dj * 32);
                mma_f16(o[2 * dj],     pa, vb4);
                mma_f16(o[2 * dj + 1], pa, vb4 + 2);
            }
        }
    }

    const float inv0 = 1.f / l0, inv1 = 1.f / l1;
    __half* ob0 = outh + (size_t)(q0 + rowl0) * DM + h * HD;
    __half* ob1 = ob0 + (size_t)8 * DM;
#pragma unroll
    for (int ni = 0; ni < 16; ni++) {
        int c = ni * 8 + 2 * lc;
        *(uint32_t*)&ob0[c] = h2pack(o[ni][0] * inv0, o[ni][1] * inv0);
        *(uint32_t*)&ob1[c] = h2pack(o[ni][2] * inv1, o[ni][3] * inv1);
    }
}

// ---------------------------------------------------------------------------
extern "C" void kernel_launch(void* const* d_in, const int* in_sizes, int n_in,
                              void* d_out, int out_size)
{
    const float* x    = (const float*)d_in[0];
    const float* wq   = (const float*)d_in[1];
    const float* wk   = (const float*)d_in[2];
    const float* wv   = (const float*)d_in[3];
    const float* wo   = (const float*)d_in[4];
    const float* fcos = (const float*)d_in[7];
    const float* fsin = (const float*)d_in[8];
    float* out = (float*)d_out;

    __half *xh, *wqh, *wkh, *wvh, *woh, *qh, *kh, *vh, *ath;
    cudaGetSymbolAddress((void**)&xh,  g_xh);
    cudaGetSymbolAddress((void**)&wqh, g_wqh);
    cudaGetSymbolAddress((void**)&wkh, g_wkh);
    cudaGetSymbolAddress((void**)&wvh, g_wvh);
    cudaGetSymbolAddress((void**)&woh, g_woh);
    cudaGetSymbolAddress((void**)&qh,  g_qh);
    cudaGetSymbolAddress((void**)&kh,  g_kh);
    cudaGetSymbolAddress((void**)&vh,  g_vh);
    cudaGetSymbolAddress((void**)&ath, g_ath);

    cudaFuncSetAttribute(qkv_gemm,
                         cudaFuncAttributeMaxDynamicSharedMemorySize, GEMM_SMEM);
    cudaFuncSetAttribute(gemm_of,
                         cudaFuncAttributeMaxDynamicSharedMemorySize, GEMM_SMEM);
    cudaFuncSetAttribute(flash_h,
                         cudaFuncAttributeMaxDynamicSharedMemorySize, FLASH_SMEM);

    // fused fp32 -> fp16 conversion
    f2h_all<<<F2H_BLOCKS, 256>>>(x, wq, wk, wv, wo, xh, wqh, wkh, wvh, woh);

    // fused QKV projection with rope epilogue (CTA 256x128)
    qkv_gemm<<<dim3(48, SEQ / 256), 256, GEMM_SMEM>>>(xh, wqh, wkh, wvh,
                                                      qh, kh, vh, fcos, fsin);

    // flash attention (BN=128)
    flash_h<<<dim3(SEQ / 128, NH), 256, FLASH_SMEM>>>(qh, kh, vh, ath);

    // output projection (CTA 256x128)
    gemm_of<<<dim3(DM / 128, SEQ / 256), 256, GEMM_SMEM>>>(ath, woh, out);
}

// round 17
// speedup vs baseline: 2.8811x; 2.8811x over previous
#include <cuda_runtime.h>
#include <cuda_fp16.h>
#include <cstdint>

#define SEQ 2048
#define DM  4096
#define NH  32
#define NKV 8
#define HD  128
#define KVD (NKV*HD)
#define NEG_BIG -1.0e9f

// half scratch buffers (static device globals)
__device__ __half g_xh [SEQ*DM];
__device__ __half g_wqh[DM*DM];
__device__ __half g_wkh[KVD*DM];
__device__ __half g_wvh[KVD*DM];
__device__ __half g_woh[DM*DM];
__device__ __half g_qh [SEQ*DM];
__device__ __half g_kh [SEQ*KVD];
__device__ __half g_vh [SEQ*KVD];
__device__ __half g_ath[SEQ*DM];

// ---------------------------------------------------------------------------
// helpers
// ---------------------------------------------------------------------------
__device__ __forceinline__ uint32_t smem_u32(const void* p) {
    uint32_t a;
    asm("{ .reg .u64 t; cvta.to.shared.u64 t, %1; cvt.u32.u64 %0, t; }"
        : "=r"(a) : "l"(p));
    return a;
}
__device__ __forceinline__ uint32_t h2pack(float a, float b) {
    __half2 h = __floats2half2_rn(a, b);
    return *reinterpret_cast<uint32_t*>(&h);
}
__device__ __forceinline__ float ex2(float x) {
    float y;
    asm("ex2.approx.f32 %0, %1;" : "=f"(y) : "f"(x));
    return y;
}
__device__ __forceinline__ void cpa16(uint32_t dst, const void* src) {
    asm volatile("cp.async.cg.shared.global [%0], [%1], 16;"
                 :: "r"(dst), "l"(src));
}
__device__ __forceinline__ void cp_commit() {
    asm volatile("cp.async.commit_group;" ::: "memory");
}
__device__ __forceinline__ void ldsm4(uint32_t* r, uint32_t addr) {
    asm volatile("ldmatrix.sync.aligned.m8n8.x4.shared.b16 {%0,%1,%2,%3}, [%4];"
                 : "=r"(r[0]), "=r"(r[1]), "=r"(r[2]), "=r"(r[3]) : "r"(addr));
}
__device__ __forceinline__ void ldsm4t(uint32_t* r, uint32_t addr) {
    asm volatile("ldmatrix.sync.aligned.m8n8.x4.trans.shared.b16 {%0,%1,%2,%3}, [%4];"
                 : "=r"(r[0]), "=r"(r[1]), "=r"(r[2]), "=r"(r[3]) : "r"(addr));
}
__device__ __forceinline__ void mma_f16(float* d, const uint32_t* a,
                                        const uint32_t* b) {
    asm volatile(
        "mma.sync.aligned.m16n8k16.row.col.f32.f16.f16.f32 "
        "{%0,%1,%2,%3},{%4,%5,%6,%7},{%8,%9},{%0,%1,%2,%3};"
        : "+f"(d[0]), "+f"(d[1]), "+f"(d[2]), "+f"(d[3])
        : "r"(a[0]), "r"(a[1]), "r"(a[2]), "r"(a[3]), "r"(b[0]), "r"(b[1]));
}

// ---------------------------------------------------------------------------
// fused fp32 -> fp16 convert of all five tensors, ILP 4
// ---------------------------------------------------------------------------
#define F4_X  2097152
#define F4_WQ 4194304
#define F4_KV 1048576
#define F4_C0 (F4_X)
#define F4_C1 (F4_C0 + F4_WQ)
#define F4_C2 (F4_C1 + F4_KV)
#define F4_C3 (F4_C2 + F4_KV)
#define F4_C4 (F4_C3 + F4_WQ)
#define F2H_BLOCKS (F4_C4 / 1024)

__global__ void f2h_all(const float* __restrict__ x,  const float* __restrict__ wq,
                        const float* __restrict__ wk, const float* __restrict__ wv,
                        const float* __restrict__ wo,
                        __half* xh, __half* wqh, __half* wkh, __half* wvh, __half* woh)
{
    size_t base = (size_t)blockIdx.x * 1024 + threadIdx.x;  // float4 index
    const float* s;
    __half* d;
    size_t off;
    if (base < F4_C0)      { s = x;  d = xh;  off = base; }
    else if (base < F4_C1) { s = wq; d = wqh; off = base - F4_C0; }
    else if (base < F4_C2) { s = wk; d = wkh; off = base - F4_C1; }
    else if (base < F4_C3) { s = wv; d = wvh; off = base - F4_C2; }
    else                   { s = wo; d = woh; off = base - F4_C3; }
#pragma unroll
    for (int j = 0; j < 4; j++) {
        size_t o4 = off + (size_t)j * 256;
        float4 v = *(const float4*)(s + o4 * 4);
        *(uint2*)(d + o4 * 4) = make_uint2(h2pack(v.x, v.y), h2pack(v.z, v.w));
    }
}

// ---------------------------------------------------------------------------
// GEMM core (R15-validated): CTA 128x128, kc=32, 128 thr = 4 warps (2Mx2N),
// warp 64x64, cp.async 4-stage with per-chunk wait_group 2 + __syncthreads,
// ldmatrix burst, fp32-acc fp16 mma. 2 CTAs/SM.
// ---------------------------------------------------------------------------
#define GSTW 5120
#define GEMM_SMEM (4*GSTW*4)       // 81920 B

#define GEMM_PRE()                                                             \
    extern __shared__ uint32_t smq[];                                          \
    const uint32_t sb = smem_u32(smq);                                         \
    const int tid  = threadIdx.x;                                              \
    const int lane = tid & 31;                                                 \
    const int warp = tid >> 5;                                                 \
    const int wm = warp & 1, wn = warp >> 1;                                   \
    const int l7 = lane & 7, l8 = (lane >> 3) & 1, l16 = lane >> 4;            \
    const int lg = lane >> 2, lc = lane & 3;                                   \
    const int r0 = tid >> 2, c0 = tid & 3;                                     \
    uint32_t dA[4], dB[4];                                                     \
    _Pragma("unroll")                                                          \
    for (int i = 0; i < 4; i++) {                                              \
        dA[i] = (uint32_t)((r0 + 32 * i) * 20 + c0 * 4) * 4;                   \
        dB[i] = dA[i] + 2560 * 4;                                              \
    }                                                                          \
    const uint32_t aoff = (uint32_t)((wm * 64 + l7 + 8 * l8) * 20 + 4 * l16) * 4; \
    const uint32_t boff = (uint32_t)(2560 + (wn * 64 + l7 + 8 * l16) * 20 + 4 * l8) * 4;

#define GLOAD(stage, koff)                                                     \
    {                                                                          \
        uint32_t base_ = sb + (uint32_t)(stage) * GSTW * 4;                    \
        _Pragma("unroll")                                                      \
        for (int i_ = 0; i_ < 4; i_++) {                                       \
            cpa16(base_ + dA[i_], Ab + (size_t)(32 * i_) * DM + (koff));       \
            cpa16(base_ + dB[i_], Bb + (size_t)(32 * i_) * DM + (koff));       \
        }                                                                      \
        cp_commit();                                                           \
    }

#define GEMM_BODY()                                                            \
    float acc[4][8][4];                                                        \
    _Pragma("unroll")                                                          \
    for (int mi = 0; mi < 4; mi++)                                             \
        _Pragma("unroll")                                                      \
        for (int ni = 0; ni < 8; ni++)                                         \
            _Pragma("unroll")                                                  \
            for (int r = 0; r < 4; r++) acc[mi][ni][r] = 0.f;                  \
    const int kiters = DM / 32;                                                \
    GLOAD(0, 0);                                                               \
    GLOAD(1, 32);                                                              \
    GLOAD(2, 64);                                                              \
    for (int kt = 0; kt < kiters; kt++) {                                      \
        if (kt + 2 < kiters)                                                   \
            asm volatile("cp.async.wait_group 2;" ::: "memory");               \
        else if (kt + 1 < kiters)                                              \
            asm volatile("cp.async.wait_group 1;" ::: "memory");               \
        else                                                                   \
            asm volatile("cp.async.wait_group 0;" ::: "memory");               \
        __syncthreads();                                                       \
        if (kt + 3 < kiters) GLOAD((kt + 3) & 3, (kt + 3) * 32);               \
        const uint32_t sbase = sb + (uint32_t)(kt & 3) * GSTW * 4;             \
        uint32_t b0f[4][4], b1f[4][4], a0f[4][4], a1f[4][4];                   \
        _Pragma("unroll")                                                      \
        for (int j = 0; j < 4; j++) ldsm4(b0f[j], sbase + boff + j * 1280);    \
        _Pragma("unroll")                                                      \
        for (int j = 0; j < 4; j++) ldsm4(a0f[j], sbase + aoff + j * 1280);    \
        _Pragma("unroll")                                                      \
        for (int j = 0; j < 4; j++) ldsm4(b1f[j], sbase + boff + j * 1280 + 32); \
        _Pragma("unroll")                                                      \
        for (int j = 0; j < 4; j++) ldsm4(a1f[j], sbase + aoff + j * 1280 + 32); \
        _Pragma("unroll")                                                      \
        for (int mi = 0; mi < 4; mi++)                                         \
            _Pragma("unroll")                                                  \
            for (int nj = 0; nj < 4; nj++) {                                   \
                mma_f16(acc[mi][2 * nj],     a0f[mi], b0f[nj]);                \
                mma_f16(acc[mi][2 * nj + 1], a0f[mi], b0f[nj] + 2);            \
            }                                                                  \
        _Pragma("unroll")                                                      \
        for (int mi = 0; mi < 4; mi++)                                         \
            _Pragma("unroll")                                                  \
            for (int nj = 0; nj < 4; nj++) {                                   \
                mma_f16(acc[mi][2 * nj],     a1f[mi], b1f[nj]);                \
                mma_f16(acc[mi][2 * nj + 1], a1f[mi], b1f[nj] + 2);            \
            }                                                                  \
    }

// fused QKV with rope epilogue on Q/K
__global__ __launch_bounds__(128, 2) void qkv_gemm(
    const __half* __restrict__ Aq,
    const __half* __restrict__ wq, const __half* __restrict__ wk,
    const __half* __restrict__ wv,
    __half* __restrict__ qo, __half* __restrict__ ko, __half* __restrict__ vo,
    const float* __restrict__ fcos, const float* __restrict__ fsin)
{
    GEMM_PRE();
    int bx = blockIdx.x;
    const __half* Bsel;
    __half* Csel;
    int Nc, cb;
    bool rope;
    if (bx < 32)      { Bsel = wq; Csel = qo; Nc = DM;  cb = bx;      rope = true; }
    else if (bx < 40) { Bsel = wk; Csel = ko; Nc = KVD; cb = bx - 32; rope = true; }
    else              { Bsel = wv; Csel = vo; Nc = KVD; cb = bx - 40; rope = false; }

    const __half* Ab = Aq + (size_t)(blockIdx.y * 128 + r0) * DM + c0 * 8;
    const __half* Bb = Bsel + (size_t)(cb * 128 + r0) * DM + c0 * 8;

    GEMM_BODY();

#pragma unroll
    for (int mi = 0; mi < 4; mi++) {
        int r = blockIdx.y * 128 + wm * 64 + mi * 16 + lg;
#pragma unroll
        for (int ni = 0; ni < 8; ni++) {
            int c = cb * 128 + wn * 64 + ni * 8 + lc * 2;
            float e0 = acc[mi][ni][0], e1 = acc[mi][ni][1];
            float e2 = acc[mi][ni][2], e3 = acc[mi][ni][3];
            if (rope) {
                int pidx = wn * 32 + ni * 4 + lc;   // pair index within head
                float c0f = fcos[r * 64 + pidx];
                float s0f = fsin[r * 64 + pidx];
                float c1f = fcos[(r + 8) * 64 + pidx];
                float s1f = fsin[(r + 8) * 64 + pidx];
                float t0 = e0 * c0f - e1 * s0f;
                float t1 = e0 * s0f + e1 * c0f;
                float t2 = e2 * c1f - e3 * s1f;
                float t3 = e2 * s1f + e3 * c1f;
                e0 = t0; e1 = t1; e2 = t2; e3 = t3;
            }
            *(uint32_t*)&Csel[(size_t)r * Nc + c]       = h2pack(e0, e1);
            *(uint32_t*)&Csel[(size_t)(r + 8) * Nc + c] = h2pack(e2, e3);
        }
    }
}

// O-projection: half in, float out
__global__ __launch_bounds__(128, 2) void gemm_of(
    const __half* __restrict__ A, const __half* __restrict__ B,
    float* __restrict__ C)
{
    GEMM_PRE();
    const int N = DM;
    const __half* Ab = A + (size_t)(blockIdx.y * 128 + r0) * DM + c0 * 8;
    const __half* Bb = B + (size_t)(blockIdx.x * 128 + r0) * DM + c0 * 8;

    GEMM_BODY();

#pragma unroll
    for (int mi = 0; mi < 4; mi++) {
        int r = blockIdx.y * 128 + wm * 64 + mi * 16 + lg;
#pragma unroll
        for (int ni = 0; ni < 8; ni++) {
            int c = blockIdx.x * 128 + wn * 64 + ni * 8 + lc * 2;
            *(float2*)&C[(size_t)r * N + c] =
                make_float2(acc[mi][ni][0], acc[mi][ni][1]);
            *(float2*)&C[(size_t)(r + 8) * N + c] =
                make_float2(acc[mi][ni][2], acc[mi][ni][3]);
        }
    }
}

// ---------------------------------------------------------------------------
// flash attention v7: BN=128, BM=128 (8 warps x 16 q rows), fp16 mma fp32-acc,
// base-2 online softmax, P-in-registers, Q fragments HOISTED into registers
// (loaded once at kb==0), cp.async double-buffered K/V.
// ---------------------------------------------------------------------------
#define QW  (128*68)
#define FTW (128*68)
#define FLASH_SMEM ((QW + 4*FTW)*4)

__global__ __launch_bounds__(256, 1) void flash_h(
    const __half* __restrict__ q, const __half* __restrict__ k,
    const __half* __restrict__ v, __half* __restrict__ outh)
{
    extern __shared__ uint32_t fsm[];
    const uint32_t sb = smem_u32(fsm);

    const int h   = blockIdx.y;
    const int qb  = gridDim.x - 1 - blockIdx.x;
    const int q0  = qb * 128;
    const int kvh = h >> 2;
    const int tid = threadIdx.x;
    const int warp = tid >> 5;
    const int lane = tid & 31;
    const int l7 = lane & 7, l8 = (lane >> 3) & 1, l16 = lane >> 4;
    const int lg = lane >> 2, lc = lane & 3;

    const int rb = tid >> 4, cch = tid & 15;

#pragma unroll
    for (int i = 0; i < 8; i++) {
        int r = i * 16 + rb;
        cpa16(sb + (uint32_t)(r * 68 + cch * 4) * 4,
              q + (size_t)(q0 + r) * DM + h * HD + cch * 8);
    }
#pragma unroll
    for (int i = 0; i < 8; i++) {
        int r = i * 16 + rb;
        cpa16(sb + (uint32_t)(QW + r * 68 + cch * 4) * 4,
              k + (size_t)r * KVD + kvh * HD + cch * 8);
        cpa16(sb + (uint32_t)(QW + 2 * FTW + r * 68 + cch * 4) * 4,
              v + (size_t)r * KVD + kvh * HD + cch * 8);
    }
    cp_commit();

    const uint32_t Qa = (uint32_t)((warp * 16 + l7 + 8 * l8) * 68 + 4 * l16) * 4;
    const uint32_t Kb = (uint32_t)((l7 + 8 * l16) * 68 + 4 * l8) * 4;
    const uint32_t Vb = (uint32_t)((l7 + 8 * l8) * 68 + 4 * l16) * 4;

    float o[16][4];
#pragma unroll
    for (int ni = 0; ni < 16; ni++)
#pragma unroll
        for (int r = 0; r < 4; r++) o[ni][r] = 0.f;
    float m0 = -3.0e38f, m1 = -3.0e38f, l0 = 0.f, l1 = 0.f;

    const float sc2 = 0.12751741f;   // 1/sqrt(128) * log2(e)
    const int rowl0 = warp * 16 + lg;

    uint32_t qreg[8][4];   // hoisted Q fragments (invariant over kb)

    for (int kb = 0; kb <= qb; kb++) {
        const int k0g = kb * 128;
        asm volatile("cp.async.wait_group 0;" ::: "memory");
        __syncthreads();

        if (kb == 0) {
#pragma unroll
            for (int kd = 0; kd < 8; kd++)
                ldsm4(qreg[kd], sb + Qa + kd * 32);
        }

        if (kb + 1 <= qb) {
            const int k0n = (kb + 1) * 128;
            const uint32_t bufn = (uint32_t)((kb + 1) & 1) * FTW;
#pragma unroll
            for (int i = 0; i < 8; i++) {
                int r = i * 16 + rb;
                cpa16(sb + (QW + bufn + (uint32_t)(r * 68 + cch * 4)) * 4,
                      k + (size_t)(k0n + r) * KVD + kvh * HD + cch * 8);
                cpa16(sb + (QW + 2 * FTW + bufn + (uint32_t)(r * 68 + cch * 4)) * 4,
                      v + (size_t)(k0n + r) * KVD + kvh * HD + cch * 8);
            }
            cp_commit();
        }

        const uint32_t bufK = sb + (QW + (uint32_t)(kb & 1) * FTW) * 4;
        const uint32_t bufV = sb + (QW + 2 * FTW + (uint32_t)(kb & 1) * FTW) * 4;

        float s[16][4];
#pragma unroll
        for (int ni = 0; ni < 16; ni++)
#pragma unroll
            for (int r = 0; r < 4; r++) s[ni][r] = 0.f;

#pragma unroll
        for (int kd = 0; kd < 8; kd++) {
#pragma unroll
            for (int nj = 0; nj < 8; nj++) {
                uint32_t kb4[4];
                ldsm4(kb4, bufK + Kb + nj * (16 * 68 * 4) + kd * 32);
                mma_f16(s[2 * nj],     qreg[kd], kb4);
                mma_f16(s[2 * nj + 1], qreg[kd], kb4 + 2);
            }
        }

        const bool diag = (kb == qb);
        float mx0 = -3.0e38f, mx1 = -3.0e38f;
#pragma unroll
        for (int ni = 0; ni < 16; ni++) {
            float v0 = s[ni][0] * sc2, v1 = s[ni][1] * sc2;
            float v2 = s[ni][2] * sc2, v3 = s[ni][3] * sc2;
            if (diag) {
                int cl = k0g + ni * 8 + 2 * lc;
                if (cl     > (q0 + rowl0))     v0 += NEG_BIG;
                if (cl + 1 > (q0 + rowl0))     v1 += NEG_BIG;
                if (cl     > (q0 + rowl0 + 8)) v2 += NEG_BIG;
                if (cl + 1 > (q0 + rowl0 + 8)) v3 += NEG_BIG;
            }
            s[ni][0] = v0; s[ni][1] = v1; s[ni][2] = v2; s[ni][3] = v3;
            mx0 = fmaxf(mx0, fmaxf(v0, v1));
            mx1 = fmaxf(mx1, fmaxf(v2, v3));
        }
        mx0 = fmaxf(mx0, __shfl_xor_sync(0xffffffffu, mx0, 1));
        mx0 = fmaxf(mx0, __shfl_xor_sync(0xffffffffu, mx0, 2));
        mx1 = fmaxf(mx1, __shfl_xor_sync(0xffffffffu, mx1, 1));
        mx1 = fmaxf(mx1, __shfl_xor_sync(0xffffffffu, mx1, 2));

        float mn0 = fmaxf(m0, mx0), mn1 = fmaxf(m1, mx1);
        float a0 = ex2(m0 - mn0), a1 = ex2(m1 - mn1);
        m0 = mn0; m1 = mn1;

        float sum0 = 0.f, sum1 = 0.f;
#pragma unroll
        for (int ni = 0; ni < 16; ni++) {
            float p0 = ex2(s[ni][0] - m0);
            float p1 = ex2(s[ni][1] - m0);
            float p2 = ex2(s[ni][2] - m1);
            float p3 = ex2(s[ni][3] - m1);
            s[ni][0] = p0; s[ni][1] = p1; s[ni][2] = p2; s[ni][3] = p3;
            sum0 += p0 + p1;
            sum1 += p2 + p3;
        }
        sum0 += __shfl_xor_sync(0xffffffffu, sum0, 1);
        sum0 += __shfl_xor_sync(0xffffffffu, sum0, 2);
        sum1 += __shfl_xor_sync(0xffffffffu, sum1, 1);
        sum1 += __shfl_xor_sync(0xffffffffu, sum1, 2);
        l0 = l0 * a0 + sum0;
        l1 = l1 * a1 + sum1;

#pragma unroll
        for (int ni = 0; ni < 16; ni++) {
            o[ni][0] *= a0; o[ni][1] *= a0;
            o[ni][2] *= a1; o[ni][3] *= a1;
        }

#pragma unroll
        for (int ks = 0; ks < 8; ks++) {
            uint32_t pa[4];
            pa[0] = h2pack(s[2 * ks][0],     s[2 * ks][1]);
            pa[1] = h2pack(s[2 * ks][2],     s[2 * ks][3]);
            pa[2] = h2pack(s[2 * ks + 1][0], s[2 * ks + 1][1]);
            pa[3] = h2pack(s[2 * ks + 1][2], s[2 * ks + 1][3]);
#pragma unroll
            for (int dj = 0; dj < 8; dj++) {
                uint32_t vb4[4];
                ldsm4t(vb4, bufV + Vb + ks * (16 * 68 * 4) + dj * 32);
                mma_f16(o[2 * dj],     pa, vb4);
                mma_f16(o[2 * dj + 1], pa, vb4 + 2);
            }
        }
    }

    const float inv0 = 1.f / l0, inv1 = 1.f / l1;
    __half* ob0 = outh + (size_t)(q0 + rowl0) * DM + h * HD;
    __half* ob1 = ob0 + (size_t)8 * DM;
#pragma unroll
    for (int ni = 0; ni < 16; ni++) {
        int c = ni * 8 + 2 * lc;
        *(uint32_t*)&ob0[c] = h2pack(o[ni][0] * inv0, o[ni][1] * inv0);
        *(uint32_t*)&ob1[c] = h2pack(o[ni][2] * inv1, o[ni][3] * inv1);
    }
}

// ---------------------------------------------------------------------------
extern "C" void kernel_launch(void* const* d_in, const int* in_sizes, int n_in,
                              void* d_out, int out_size)
{
    const float* x    = (const float*)d_in[0];
    const float* wq   = (const float*)d_in[1];
    const float* wk   = (const float*)d_in[2];
    const float* wv   = (const float*)d_in[3];
    const float* wo   = (const float*)d_in[4];
    const float* fcos = (const float*)d_in[7];
    const float* fsin = (const float*)d_in[8];
    float* out = (float*)d_out;

    __half *xh, *wqh, *wkh, *wvh, *woh, *qh, *kh, *vh, *ath;
    cudaGetSymbolAddress((void**)&xh,  g_xh);
    cudaGetSymbolAddress((void**)&wqh, g_wqh);
    cudaGetSymbolAddress((void**)&wkh, g_wkh);
    cudaGetSymbolAddress((void**)&wvh, g_wvh);
    cudaGetSymbolAddress((void**)&woh, g_woh);
    cudaGetSymbolAddress((void**)&qh,  g_qh);
    cudaGetSymbolAddress((void**)&kh,  g_kh);
    cudaGetSymbolAddress((void**)&vh,  g_vh);
    cudaGetSymbolAddress((void**)&ath, g_ath);

    cudaFuncSetAttribute(qkv_gemm,
                         cudaFuncAttributeMaxDynamicSharedMemorySize, GEMM_SMEM);
    cudaFuncSetAttribute(gemm_of,
                         cudaFuncAttributeMaxDynamicSharedMemorySize, GEMM_SMEM);
    cudaFuncSetAttribute(flash_h,
                         cudaFuncAttributeMaxDynamicSharedMemorySize, FLASH_SMEM);

    // fused fp32 -> fp16 conversion
    f2h_all<<<F2H_BLOCKS, 256>>>(x, wq, wk, wv, wo, xh, wqh, wkh, wvh, woh);

    // fused QKV projection with rope epilogue
    qkv_gemm<<<dim3(48, SEQ / 128), 128, GEMM_SMEM>>>(xh, wqh, wkh, wvh,
                                                      qh, kh, vh, fcos, fsin);

    // flash attention (BN=128, hoisted Q fragments)
    flash_h<<<dim3(SEQ / 128, NH), 256, FLASH_SMEM>>>(qh, kh, vh, ath);

    // output projection
    gemm_of<<<dim3(DM / 128, SEQ / 128), 128, GEMM_SMEM>>>(ath, woh, out);
}